// round 13
// baseline (speedup 1.0000x reference)
#include <cuda_runtime.h>
#include <cstdint>

#define N_B   32
#define C_DIM 256
#define HW    1024
#define S_DIM 64

// ---------------- scratch (device globals; no allocations allowed) ----------------
__device__ float d_segs[N_B * S_DIM * HW];     // seg_s  (n, s*hw flat)
__device__ float d_segc[N_B * S_DIM * HW];     // seg_c
__device__ float d_mean[N_B * C_DIM];
__device__ float d_a[N_B * S_DIM];             // ch_att
__device__ float d_u[N_B * HW];
__device__ float d_v[N_B * HW];
__device__ float d_mc[N_B * HW];               // column max, branch c
__device__ float d_e[N_B * HW];                // edge_mm (per p)
__device__ float d_g[N_B * HW];                // seg_ss  (per q)
__device__ float d_S[(size_t)N_B * HW * HW];   // sigma_out -> similarity (in-place)
__device__ float d_segsim[N_B * C_DIM * HW];

// ---------------- tf32 helpers ----------------
__device__ __forceinline__ uint32_t to_tf32(float x) {
    uint32_t r;
    asm("cvt.rna.tf32.f32 %0, %1;" : "=r"(r) : "f"(x));
    return r;
}
__device__ __forceinline__ void split_tf32(float x, uint32_t& hi, uint32_t& lo) {
    hi = to_tf32(x);
    lo = to_tf32(x - __uint_as_float(hi));
}
__device__ __forceinline__ void mma_tf32(float* c, const uint32_t* a, const uint32_t* b) {
    asm volatile(
        "mma.sync.aligned.m16n8k8.row.col.f32.tf32.tf32.f32 "
        "{%0,%1,%2,%3}, {%4,%5,%6,%7}, {%8,%9}, {%0,%1,%2,%3};"
        : "+f"(c[0]), "+f"(c[1]), "+f"(c[2]), "+f"(c[3])
        : "r"(a[0]), "r"(a[1]), "r"(a[2]), "r"(a[3]), "r"(b[0]), "r"(b[1]));
}

// ---------------- small kernels ----------------
__global__ void k_mean(const float* __restrict__ seg) {
    int n = blockIdx.x >> 8, c = blockIdx.x & 255;
    const float* p = seg + ((size_t)n * C_DIM + c) * HW;
    float s = 0.f;
    for (int i = threadIdx.x; i < HW; i += 256) s += p[i];
    __shared__ float sm[8];
    for (int o = 16; o > 0; o >>= 1) s += __shfl_down_sync(~0u, s, o);
    if ((threadIdx.x & 31) == 0) sm[threadIdx.x >> 5] = s;
    __syncthreads();
    if (threadIdx.x == 0) {
        float t = 0.f;
        #pragma unroll
        for (int i = 0; i < 8; i++) t += sm[i];
        d_mean[n * C_DIM + c] = t * (1.0f / HW);
    }
}

__global__ void k_chatt(const float* __restrict__ Wm, const float* __restrict__ bm) {
    int n = blockIdx.x;
    __shared__ float mn[C_DIM];
    for (int i = threadIdx.x; i < C_DIM; i += 64) mn[i] = d_mean[n * C_DIM + i];
    __syncthreads();
    int s = threadIdx.x;
    float acc = bm[s];
    const float* w = Wm + s * C_DIM;
    #pragma unroll 8
    for (int c = 0; c < C_DIM; c++) acc = fmaf(mn[c], w[c], acc);
    d_a[n * S_DIM + s] = fmaxf(acc, 0.f);
}

__global__ void k_pool(const float* __restrict__ seg, const float* __restrict__ edge,
                       const float* __restrict__ ws2, const float* __restrict__ bs2,
                       const float* __restrict__ ws3, const float* __restrict__ bs3) {
    int p = blockIdx.x * 256 + threadIdx.x;
    int n = blockIdx.y;
    const float* sp = seg  + (size_t)n * C_DIM * HW + p;
    const float* ep = edge + (size_t)n * C_DIM * HW + p;
    float ms = -3.0e38f, me = -3.0e38f;
    #pragma unroll 4
    for (int c = 0; c < C_DIM; c++) {
        float sv = sp[c * HW], ev = ep[c * HW];
        ms = fmaxf(ms, sv);
        me = fmaxf(me, sv * ev);
    }
    d_g[n * HW + p] = ms * ws2[0] + bs2[0];
    d_e[n * HW + p] = me * ws3[0] + bs3[0];
}

__global__ void k_uv() {
    int n = blockIdx.x, t = threadIdx.x;
    __shared__ float sa[S_DIM];
    __shared__ float smax[32], smin[32];
    if (t < S_DIM) sa[t] = d_a[n * S_DIM + t];
    __syncthreads();
    const float* F = d_segs + n * S_DIM * HW;
    float u = 0.f;
    const float* row = F + t * S_DIM;
    #pragma unroll
    for (int k = 0; k < S_DIM; k++) u = fmaf(row[k], sa[k], u);
    d_u[n * HW + t] = u;
    float um = u, un = u;
    for (int o = 16; o > 0; o >>= 1) {
        um = fmaxf(um, __shfl_xor_sync(~0u, um, o));
        un = fminf(un, __shfl_xor_sync(~0u, un, o));
    }
    if ((t & 31) == 0) { smax[t >> 5] = um; smin[t >> 5] = un; }
    __syncthreads();
    if (t < 32) {
        float a1 = smax[t], b1 = smin[t];
        for (int o = 16; o > 0; o >>= 1) {
            a1 = fmaxf(a1, __shfl_xor_sync(~0u, a1, o));
            b1 = fminf(b1, __shfl_xor_sync(~0u, b1, o));
        }
        if (t == 0) { smax[0] = a1; smin[0] = b1; }
    }
    __syncthreads();
    float Umax = smax[0], Umin = smin[0];
    float v = 0.f;
    #pragma unroll
    for (int k = 0; k < S_DIM; k++) v = fmaf(sa[k], F[k * HW + t], v);
    d_v[n * HW + t]  = v;
    d_mc[n * HW + t] = (v >= 0.f) ? v * Umax : v * Umin;
}

// ======== split-3 tf32 mma machinery (128x128 block, 8 warps @ 64x32, pitch 136) ========
#define TMMA_IDX()                                            \
    const int tid = threadIdx.x;                              \
    const int lane = tid & 31;                                \
    const int wrp = tid >> 5;                                 \
    const int wm = (wrp & 1) * 64;                            \
    const int wn = (wrp >> 1) * 32;                           \
    const int g = lane >> 2, tg = lane & 3;                   \
    float acc[4][4][4];                                       \
    _Pragma("unroll") for (int i_ = 0; i_ < 4; i_++)          \
    _Pragma("unroll") for (int j_ = 0; j_ < 4; j_++)          \
    _Pragma("unroll") for (int r_ = 0; r_ < 4; r_++) acc[i_][j_][r_] = 0.f;

#define TMMA3_DECL()                                          \
    __shared__ uint32_t Ah[16][136], Al[16][136];             \
    __shared__ uint32_t Bh[16][136], Bl[16][136];             \
    TMMA_IDX()

#define TMMA3_COMPUTE()                                       \
    __syncthreads();                                          \
    _Pragma("unroll")                                         \
    for (int ks = 0; ks < 16; ks += 8) {                      \
        uint32_t ah[4][4], al[4][4], bh[4][2], bl[4][2];      \
        _Pragma("unroll")                                     \
        for (int im = 0; im < 4; im++) {                      \
            int mr = wm + im * 16 + g;                        \
            ah[im][0] = Ah[ks + tg][mr];                      \
            ah[im][1] = Ah[ks + tg][mr + 8];                  \
            ah[im][2] = Ah[ks + tg + 4][mr];                  \
            ah[im][3] = Ah[ks + tg + 4][mr + 8];              \
            al[im][0] = Al[ks + tg][mr];                      \
            al[im][1] = Al[ks + tg][mr + 8];                  \
            al[im][2] = Al[ks + tg + 4][mr];                  \
            al[im][3] = Al[ks + tg + 4][mr + 8];              \
        }                                                     \
        _Pragma("unroll")                                     \
        for (int jn = 0; jn < 4; jn++) {                      \
            int nc = wn + jn * 8 + g;                         \
            bh[jn][0] = Bh[ks + tg][nc];                      \
            bh[jn][1] = Bh[ks + tg + 4][nc];                  \
            bl[jn][0] = Bl[ks + tg][nc];                      \
            bl[jn][1] = Bl[ks + tg + 4][nc];                  \
        }                                                     \
        _Pragma("unroll")                                     \
        for (int im = 0; im < 4; im++)                        \
        _Pragma("unroll")                                     \
        for (int jn = 0; jn < 4; jn++) {                      \
            mma_tf32(acc[im][jn], ah[im], bl[jn]);            \
            mma_tf32(acc[im][jn], al[im], bh[jn]);            \
            mma_tf32(acc[im][jn], ah[im], bh[jn]);            \
        }                                                     \
    }                                                         \
    __syncthreads();

// seg_s / seg_c : [128 stacked s-rows] x [1024 p], K = 256 (split-3 tf32, 2 CTA/SM)
__global__ __launch_bounds__(256, 2) void k_seggemm3(
    const float* __restrict__ seg,
    const float* __restrict__ Ws1, const float* __restrict__ bs1,
    const float* __restrict__ Ws11, const float* __restrict__ bs11) {
    const int n = blockIdx.y;
    const int q0 = blockIdx.x * 128;
    const float* segn = seg + (size_t)n * C_DIM * HW;
    TMMA3_DECL();
    for (int k0 = 0; k0 < C_DIM; k0 += 16) {
        #pragma unroll
        for (int i = 0; i < 8; i++) {
            int e = tid + i * 256, kk = e & 15, m = e >> 4;
            float w = (m < 64) ? Ws1[m * 256 + k0 + kk]
                               : Ws11[(m - 64) * 256 + k0 + kk];
            split_tf32(w, Ah[kk][m], Al[kk][m]);
        }
        #pragma unroll
        for (int i = 0; i < 8; i++) {
            int e = tid + i * 256, kk = e >> 7, j = e & 127;
            split_tf32(segn[(k0 + kk) * HW + q0 + j], Bh[kk][j], Bl[kk][j]);
        }
        TMMA3_COMPUTE();
    }
    #pragma unroll
    for (int im = 0; im < 4; im++) {
        int m = wm + im * 16 + g;
        #pragma unroll
        for (int rr = 0; rr < 2; rr++) {
            int mr = m + rr * 8;
            float bias = (mr < 64) ? bs1[mr] : bs11[mr - 64];
            float* dst = (mr < 64) ? (d_segs + n * S_DIM * HW + mr * HW)
                                   : (d_segc + n * S_DIM * HW + (mr - 64) * HW);
            #pragma unroll
            for (int jn = 0; jn < 4; jn++) {
                int q = q0 + wn + jn * 8 + 2 * tg;
                *(float2*)&dst[q] = make_float2(acc[im][jn][rr * 2] + bias,
                                                acc[im][jn][rr * 2 + 1] + bias);
            }
        }
    }
}

// sigma_out : S[p,q] = sum_t F[p*64+t] * F[t*1024+q]  (split-3 tf32, ~fp32 accurate)
__global__ __launch_bounds__(256, 2) void k_sgemm3() {
    const int n = blockIdx.z;
    const float* F = d_segc + n * S_DIM * HW;
    const int p0 = blockIdx.y * 128, q0 = blockIdx.x * 128;
    TMMA3_DECL();
    for (int k0 = 0; k0 < S_DIM; k0 += 16) {
        #pragma unroll
        for (int i = 0; i < 8; i++) {
            int e = tid + i * 256, kk = e & 15, m = e >> 4;
            split_tf32(F[(p0 + m) * S_DIM + k0 + kk], Ah[kk][m], Al[kk][m]);
        }
        #pragma unroll
        for (int i = 0; i < 8; i++) {
            int e = tid + i * 256, kk = e >> 7, j = e & 127;
            split_tf32(F[(k0 + kk) * HW + q0 + j], Bh[kk][j], Bl[kk][j]);
        }
        TMMA3_COMPUTE();
    }
    float* C = d_S + (size_t)n * HW * HW;
    #pragma unroll
    for (int im = 0; im < 4; im++) {
        int m = p0 + wm + im * 16 + g;
        #pragma unroll
        for (int jn = 0; jn < 4; jn++) {
            int q = q0 + wn + jn * 8 + 2 * tg;
            *(float2*)&C[(size_t)m * HW + q]       = make_float2(acc[im][jn][0], acc[im][jn][1]);
            *(float2*)&C[(size_t)(m + 8) * HW + q] = make_float2(acc[im][jn][2], acc[im][jn][3]);
        }
    }
}

// stats (factored max, chain-free) + combine fused; MUFU exp; in-place over d_S
__global__ void k_stats(/*grid (8, N_B), 128 thr*/) {
    int n = blockIdx.y;
    int q = blockIdx.x * 128 + threadIdx.x;
    __shared__ float su[HW], se[HW];
    for (int i = threadIdx.x; i < HW; i += 128) {
        su[i] = d_u[n * HW + i];
        se[i] = d_e[n * HW + i];
    }
    __syncthreads();
    float vq = d_v[n * HW + q], mcq = d_mc[n * HW + q], gq = d_g[n * HW + q];
    float* Scol = d_S + (size_t)n * HW * HW + q;

    // pass 1: min/max of t = e_p * sigma  (no exp; 4-cyc chains, memory-bound)
    float Mp = -3.0e38f, Mn = 3.0e38f;
    #pragma unroll 8
    for (int p = 0; p < HW; p++) {
        float t = se[p] * Scol[(size_t)p * HW];
        Mp = fmaxf(Mp, t);
        Mn = fminf(Mn, t);
    }
    float ms = (gq >= 0.f) ? gq * Mp : gq * Mn;

    // pass 2: Zc + Zs via MUFU exp (independent, pipelined, off the fma pipe)
    float Zc = 0.f, Zs = 0.f;
    #pragma unroll 4
    for (int p = 0; p < HW; p++) {
        float t = se[p] * Scol[(size_t)p * HW];
        Zc += __expf(fmaf(su[p], vq, -mcq));
        Zs += __expf(fmaf(gq, t, -ms));
    }
    float rZc = 1.0f / Zc, rZs = 1.0f / Zs;

    // pass 3: combine, in place (this thread owns column q exclusively)
    #pragma unroll 4
    for (int p = 0; p < HW; p++) {
        float s = Scol[(size_t)p * HW];
        float val = __expf(fmaf(su[p], vq, -mcq)) * rZc
                  + __expf(fmaf(gq * se[p], s, -ms)) * rZs;
        Scol[(size_t)p * HW] = val;
    }
}

// ======== plain tf32 mma (128x128 block, 8 warps @ 64x32) — R10-proven ========
#define TMMA_DECL()                                           \
    __shared__ uint32_t As[16][136];                          \
    __shared__ uint32_t Bsh[16][136];                         \
    TMMA_IDX()

#define TMMA_COMPUTE()                                        \
    __syncthreads();                                          \
    _Pragma("unroll")                                         \
    for (int ks = 0; ks < 16; ks += 8) {                      \
        uint32_t af[4][4], bfr[4][2];                         \
        _Pragma("unroll")                                     \
        for (int im = 0; im < 4; im++) {                      \
            int mr = wm + im * 16 + g;                        \
            af[im][0] = As[ks + tg][mr];                      \
            af[im][1] = As[ks + tg][mr + 8];                  \
            af[im][2] = As[ks + tg + 4][mr];                  \
            af[im][3] = As[ks + tg + 4][mr + 8];              \
        }                                                     \
        _Pragma("unroll")                                     \
        for (int jn = 0; jn < 4; jn++) {                      \
            int nc = wn + jn * 8 + g;                         \
            bfr[jn][0] = Bsh[ks + tg][nc];                    \
            bfr[jn][1] = Bsh[ks + tg + 4][nc];                \
        }                                                     \
        _Pragma("unroll")                                     \
        for (int im = 0; im < 4; im++)                        \
        _Pragma("unroll")                                     \
        for (int jn = 0; jn < 4; jn++)                        \
            mma_tf32(acc[im][jn], af[im], bfr[jn]);           \
    }                                                         \
    __syncthreads();

// seg_sim = seg2 @ similarity  (plain tf32 mma, trivial staging)
__global__ __launch_bounds__(256, 2) void k_bmm_t(const float* __restrict__ seg) {
    const int n = blockIdx.z;
    const int m0 = blockIdx.y * 128, q0 = blockIdx.x * 128;
    const float* A = seg + (size_t)n * C_DIM * HW;
    const float* B = d_S + (size_t)n * HW * HW;
    TMMA_DECL();
    for (int k0 = 0; k0 < HW; k0 += 16) {
        #pragma unroll
        for (int i = 0; i < 8; i++) {
            int e = tid + i * 256, kk = e & 15, m = e >> 4;
            As[kk][m] = to_tf32(A[(m0 + m) * HW + k0 + kk]);
        }
        #pragma unroll
        for (int i = 0; i < 8; i++) {
            int e = tid + i * 256, kk = e >> 7, j = e & 127;
            Bsh[kk][j] = to_tf32(B[(size_t)(k0 + kk) * HW + q0 + j]);
        }
        TMMA_COMPUTE();
    }
    float* C = d_segsim + (size_t)n * C_DIM * HW;
    #pragma unroll
    for (int im = 0; im < 4; im++) {
        int m = m0 + wm + im * 16 + g;
        #pragma unroll
        for (int jn = 0; jn < 4; jn++) {
            int q = q0 + wn + jn * 8 + 2 * tg;
            *(float2*)&C[(size_t)m * HW + q]       = make_float2(acc[im][jn][0], acc[im][jn][1]);
            *(float2*)&C[(size_t)(m + 8) * HW + q] = make_float2(acc[im][jn][2], acc[im][jn][3]);
        }
    }
}

// out = relu(W_g @ seg_sim + b_g) + 2*seg  (tf32 mma)
__global__ __launch_bounds__(256, 2) void k_final_t(
    const float* __restrict__ Wg, const float* __restrict__ bg,
    const float* __restrict__ seg, float* __restrict__ out) {
    const int n = blockIdx.z;
    const int m0 = blockIdx.y * 128, q0 = blockIdx.x * 128;
    const float* B = d_segsim + (size_t)n * C_DIM * HW;
    TMMA_DECL();
    for (int k0 = 0; k0 < C_DIM; k0 += 16) {
        #pragma unroll
        for (int i = 0; i < 8; i++) {
            int e = tid + i * 256, kk = e & 15, m = e >> 4;
            As[kk][m] = to_tf32(Wg[(m0 + m) * C_DIM + k0 + kk]);
        }
        #pragma unroll
        for (int i = 0; i < 8; i++) {
            int e = tid + i * 256, kk = e >> 7, j = e & 127;
            Bsh[kk][j] = to_tf32(B[(k0 + kk) * HW + q0 + j]);
        }
        TMMA_COMPUTE();
    }
    const float* segn = seg + (size_t)n * C_DIM * HW;
    float* outn = out + (size_t)n * C_DIM * HW;
    #pragma unroll
    for (int im = 0; im < 4; im++) {
        int m = m0 + wm + im * 16 + g;
        float b0 = bg[m], b1 = bg[m + 8];
        #pragma unroll
        for (int jn = 0; jn < 4; jn++) {
            int q = q0 + wn + jn * 8 + 2 * tg;
            float2 s0 = *(const float2*)&segn[m * HW + q];
            float2 s1 = *(const float2*)&segn[(m + 8) * HW + q];
            float2 r0, r1;
            r0.x = fmaxf(acc[im][jn][0] + b0, 0.f) + 2.f * s0.x;
            r0.y = fmaxf(acc[im][jn][1] + b0, 0.f) + 2.f * s0.y;
            r1.x = fmaxf(acc[im][jn][2] + b1, 0.f) + 2.f * s1.x;
            r1.y = fmaxf(acc[im][jn][3] + b1, 0.f) + 2.f * s1.y;
            *(float2*)&outn[m * HW + q] = r0;
            *(float2*)&outn[(m + 8) * HW + q] = r1;
        }
    }
}

// ---------------- launch ----------------
extern "C" void kernel_launch(void* const* d_in, const int* in_sizes, int n_in,
                              void* d_out, int out_size) {
    const float* seg  = (const float*)d_in[0];
    const float* edge = (const float*)d_in[1];
    const float* Ws1  = (const float*)d_in[2];
    const float* bs1  = (const float*)d_in[3];
    const float* Ws11 = (const float*)d_in[4];
    const float* bs11 = (const float*)d_in[5];
    const float* Wmlp = (const float*)d_in[6];
    const float* bmlp = (const float*)d_in[7];
    const float* ws2  = (const float*)d_in[8];
    const float* bs2  = (const float*)d_in[9];
    const float* ws3  = (const float*)d_in[10];
    const float* bs3  = (const float*)d_in[11];
    const float* Wg   = (const float*)d_in[12];
    const float* bg   = (const float*)d_in[13];
    float* out = (float*)d_out;

    k_mean    <<<N_B * C_DIM, 256>>>(seg);
    k_chatt   <<<N_B, 64>>>(Wmlp, bmlp);
    k_pool    <<<dim3(4, N_B), 256>>>(seg, edge, ws2, bs2, ws3, bs3);
    k_seggemm3<<<dim3(8, N_B), 256>>>(seg, Ws1, bs1, Ws11, bs11);
    k_uv      <<<N_B, 1024>>>();
    k_sgemm3  <<<dim3(8, 8, N_B), 256>>>();
    k_stats   <<<dim3(8, N_B), 128>>>();
    k_bmm_t   <<<dim3(8, 2, N_B), 256>>>(seg);
    k_final_t <<<dim3(8, 2, N_B), 256>>>(Wg, bg, seg, out);
}

// round 14
// speedup vs baseline: 1.2826x; 1.2826x over previous
#include <cuda_runtime.h>
#include <cstdint>

#define N_B   32
#define C_DIM 256
#define HW    1024
#define S_DIM 64

// ---------------- scratch (device globals; no allocations allowed) ----------------
__device__ float d_segs[N_B * S_DIM * HW];     // seg_s  (n, s*hw flat)
__device__ float d_segc[N_B * S_DIM * HW];     // seg_c
__device__ float d_mean[N_B * C_DIM];
__device__ float d_a[N_B * S_DIM];             // ch_att
__device__ float d_u[N_B * HW];
__device__ float d_v[N_B * HW];
__device__ float d_mc[N_B * HW];               // column max, branch c
__device__ float d_e[N_B * HW];                // edge_mm (per p)
__device__ float d_g[N_B * HW];                // seg_ss  (per q)
__device__ float d_rZc[N_B * HW];
__device__ float d_ms[N_B * HW];
__device__ float d_rZs[N_B * HW];
__device__ float d_S[(size_t)N_B * HW * HW];   // sigma_out -> similarity (in-place)
__device__ float d_segsim[N_B * C_DIM * HW];

// ---------------- fast exp on the FMA pipe ----------------
__device__ __forceinline__ float fexp(float x) {
    float z = fmaxf(x * 1.442695041f, -126.0f);
    int   zi = __float2int_rn(z);
    float f  = z - (float)zi;
    float p  = 0.000154035304f;
    p = fmaf(p, f, 0.00133335581f);
    p = fmaf(p, f, 0.00961812910f);
    p = fmaf(p, f, 0.0555041087f);
    p = fmaf(p, f, 0.240226507f);
    p = fmaf(p, f, 0.693147181f);
    p = fmaf(p, f, 1.0f);
    return __int_as_float((zi + 127) << 23) * p;
}

// ---------------- tf32 helpers ----------------
__device__ __forceinline__ uint32_t to_tf32(float x) {
    uint32_t r;
    asm("cvt.rna.tf32.f32 %0, %1;" : "=r"(r) : "f"(x));
    return r;
}
__device__ __forceinline__ void split_tf32(float x, uint32_t& hi, uint32_t& lo) {
    hi = to_tf32(x);
    lo = to_tf32(x - __uint_as_float(hi));
}
__device__ __forceinline__ void mma_tf32(float* c, const uint32_t* a, const uint32_t* b) {
    asm volatile(
        "mma.sync.aligned.m16n8k8.row.col.f32.tf32.tf32.f32 "
        "{%0,%1,%2,%3}, {%4,%5,%6,%7}, {%8,%9}, {%0,%1,%2,%3};"
        : "+f"(c[0]), "+f"(c[1]), "+f"(c[2]), "+f"(c[3])
        : "r"(a[0]), "r"(a[1]), "r"(a[2]), "r"(a[3]), "r"(b[0]), "r"(b[1]));
}
__device__ __forceinline__ void cp16(void* s, const void* g) {
    uint32_t sa = (uint32_t)__cvta_generic_to_shared(s);
    asm volatile("cp.async.cg.shared.global [%0], [%1], 16;" :: "r"(sa), "l"(g));
}

// ---------------- small kernels ----------------
__global__ void k_mean(const float* __restrict__ seg) {
    int n = blockIdx.x >> 8, c = blockIdx.x & 255;
    const float* p = seg + ((size_t)n * C_DIM + c) * HW;
    float s = 0.f;
    for (int i = threadIdx.x; i < HW; i += 256) s += p[i];
    __shared__ float sm[8];
    for (int o = 16; o > 0; o >>= 1) s += __shfl_down_sync(~0u, s, o);
    if ((threadIdx.x & 31) == 0) sm[threadIdx.x >> 5] = s;
    __syncthreads();
    if (threadIdx.x == 0) {
        float t = 0.f;
        #pragma unroll
        for (int i = 0; i < 8; i++) t += sm[i];
        d_mean[n * C_DIM + c] = t * (1.0f / HW);
    }
}

__global__ void k_chatt(const float* __restrict__ Wm, const float* __restrict__ bm) {
    int n = blockIdx.x;
    __shared__ float mn[C_DIM];
    for (int i = threadIdx.x; i < C_DIM; i += 64) mn[i] = d_mean[n * C_DIM + i];
    __syncthreads();
    int s = threadIdx.x;
    float acc = bm[s];
    const float* w = Wm + s * C_DIM;
    #pragma unroll 8
    for (int c = 0; c < C_DIM; c++) acc = fmaf(mn[c], w[c], acc);
    d_a[n * S_DIM + s] = fmaxf(acc, 0.f);
}

__global__ void k_pool(const float* __restrict__ seg, const float* __restrict__ edge,
                       const float* __restrict__ ws2, const float* __restrict__ bs2,
                       const float* __restrict__ ws3, const float* __restrict__ bs3) {
    int p = blockIdx.x * 256 + threadIdx.x;
    int n = blockIdx.y;
    const float* sp = seg  + (size_t)n * C_DIM * HW + p;
    const float* ep = edge + (size_t)n * C_DIM * HW + p;
    float ms = -3.0e38f, me = -3.0e38f;
    #pragma unroll 4
    for (int c = 0; c < C_DIM; c++) {
        float sv = sp[c * HW], ev = ep[c * HW];
        ms = fmaxf(ms, sv);
        me = fmaxf(me, sv * ev);
    }
    d_g[n * HW + p] = ms * ws2[0] + bs2[0];
    d_e[n * HW + p] = me * ws3[0] + bs3[0];
}

__global__ void k_uv() {
    int n = blockIdx.x, t = threadIdx.x;
    __shared__ float sa[S_DIM];
    __shared__ float smax[32], smin[32];
    if (t < S_DIM) sa[t] = d_a[n * S_DIM + t];
    __syncthreads();
    const float* F = d_segs + n * S_DIM * HW;
    float u = 0.f;
    const float* row = F + t * S_DIM;
    #pragma unroll
    for (int k = 0; k < S_DIM; k++) u = fmaf(row[k], sa[k], u);
    d_u[n * HW + t] = u;
    float um = u, un = u;
    for (int o = 16; o > 0; o >>= 1) {
        um = fmaxf(um, __shfl_xor_sync(~0u, um, o));
        un = fminf(un, __shfl_xor_sync(~0u, un, o));
    }
    if ((t & 31) == 0) { smax[t >> 5] = um; smin[t >> 5] = un; }
    __syncthreads();
    if (t < 32) {
        float a1 = smax[t], b1 = smin[t];
        for (int o = 16; o > 0; o >>= 1) {
            a1 = fmaxf(a1, __shfl_xor_sync(~0u, a1, o));
            b1 = fminf(b1, __shfl_xor_sync(~0u, b1, o));
        }
        if (t == 0) { smax[0] = a1; smin[0] = b1; }
    }
    __syncthreads();
    float Umax = smax[0], Umin = smin[0];
    float v = 0.f;
    #pragma unroll
    for (int k = 0; k < S_DIM; k++) v = fmaf(sa[k], F[k * HW + t], v);
    d_v[n * HW + t]  = v;
    d_mc[n * HW + t] = (v >= 0.f) ? v * Umax : v * Umin;
}

// ---------------- fp32 128x128 tiled SGEMM (BK=16, 256 thr, 8x8/thread) ----------------
#define GEMM_PROLOG()                                         \
    __shared__ float Asf[16][132];                            \
    __shared__ float Bsf[16][128];                            \
    const int tid = threadIdx.x;                              \
    const int ty = tid >> 4, tx = tid & 15;                   \
    float acc[8][8];                                          \
    _Pragma("unroll") for (int i = 0; i < 8; i++)             \
    _Pragma("unroll") for (int j = 0; j < 8; j++) acc[i][j] = 0.f;

#define GEMM_MAINLOOP()                                       \
    __syncthreads();                                          \
    _Pragma("unroll")                                         \
    for (int kk = 0; kk < 16; kk++) {                         \
        float a[8], b[8];                                     \
        *(float4*)&a[0] = *(const float4*)&Asf[kk][ty * 8];   \
        *(float4*)&a[4] = *(const float4*)&Asf[kk][ty * 8 + 4];\
        *(float4*)&b[0] = *(const float4*)&Bsf[kk][tx * 8];   \
        *(float4*)&b[4] = *(const float4*)&Bsf[kk][tx * 8 + 4];\
        _Pragma("unroll") for (int i = 0; i < 8; i++)         \
        _Pragma("unroll") for (int j = 0; j < 8; j++)         \
            acc[i][j] = fmaf(a[i], b[j], acc[i][j]);          \
    }                                                         \
    __syncthreads();

// sigma_out : S[p,q] = sum_t F[p*64+t] * F[t*1024+q]  (fp32: logit sensitivity; R10-proven)
__global__ __launch_bounds__(256, 2) void k_sgemm() {
    const int n = blockIdx.z;
    const float* F = d_segc + n * S_DIM * HW;
    const int p0 = blockIdx.y * 128, q0 = blockIdx.x * 128;
    GEMM_PROLOG();
    for (int k0 = 0; k0 < S_DIM; k0 += 16) {
        #pragma unroll
        for (int i = 0; i < 8; i++) {
            int e = tid + i * 256, kk = e & 15, m = e >> 4;
            Asf[kk][m] = F[(p0 + m) * S_DIM + k0 + kk];
        }
        #pragma unroll
        for (int i = 0; i < 8; i++) {
            int e = tid + i * 256, kk = e >> 7, j = e & 127;
            Bsf[kk][j] = F[(k0 + kk) * HW + q0 + j];
        }
        GEMM_MAINLOOP();
    }
    float* C = d_S + (size_t)n * HW * HW;
    #pragma unroll
    for (int i = 0; i < 8; i++) {
        float* dst = C + (size_t)(p0 + ty * 8 + i) * HW + q0 + tx * 8;
        *(float4*)&dst[0] = make_float4(acc[i][0], acc[i][1], acc[i][2], acc[i][3]);
        *(float4*)&dst[4] = make_float4(acc[i][4], acc[i][5], acc[i][6], acc[i][7]);
    }
}

// ======== split-3 tf32 mma machinery (128x128 block, 8 warps @ 64x32, pitch 136) ========
#define TMMA_IDX()                                            \
    const int tid = threadIdx.x;                              \
    const int lane = tid & 31;                                \
    const int wrp = tid >> 5;                                 \
    const int wm = (wrp & 1) * 64;                            \
    const int wn = (wrp >> 1) * 32;                           \
    const int g = lane >> 2, tg = lane & 3;                   \
    float acc[4][4][4];                                       \
    _Pragma("unroll") for (int i_ = 0; i_ < 4; i_++)          \
    _Pragma("unroll") for (int j_ = 0; j_ < 4; j_++)          \
    _Pragma("unroll") for (int r_ = 0; r_ < 4; r_++) acc[i_][j_][r_] = 0.f;

#define TMMA3_DECL()                                          \
    __shared__ uint32_t Ah[16][136], Al[16][136];             \
    __shared__ uint32_t Bh[16][136], Bl[16][136];             \
    TMMA_IDX()

#define TMMA3_COMPUTE()                                       \
    __syncthreads();                                          \
    _Pragma("unroll")                                         \
    for (int ks = 0; ks < 16; ks += 8) {                      \
        uint32_t ah[4][4], al[4][4], bh[4][2], bl[4][2];      \
        _Pragma("unroll")                                     \
        for (int im = 0; im < 4; im++) {                      \
            int mr = wm + im * 16 + g;                        \
            ah[im][0] = Ah[ks + tg][mr];                      \
            ah[im][1] = Ah[ks + tg][mr + 8];                  \
            ah[im][2] = Ah[ks + tg + 4][mr];                  \
            ah[im][3] = Ah[ks + tg + 4][mr + 8];              \
            al[im][0] = Al[ks + tg][mr];                      \
            al[im][1] = Al[ks + tg][mr + 8];                  \
            al[im][2] = Al[ks + tg + 4][mr];                  \
            al[im][3] = Al[ks + tg + 4][mr + 8];              \
        }                                                     \
        _Pragma("unroll")                                     \
        for (int jn = 0; jn < 4; jn++) {                      \
            int nc = wn + jn * 8 + g;                         \
            bh[jn][0] = Bh[ks + tg][nc];                      \
            bh[jn][1] = Bh[ks + tg + 4][nc];                  \
            bl[jn][0] = Bl[ks + tg][nc];                      \
            bl[jn][1] = Bl[ks + tg + 4][nc];                  \
        }                                                     \
        _Pragma("unroll")                                     \
        for (int im = 0; im < 4; im++)                        \
        _Pragma("unroll")                                     \
        for (int jn = 0; jn < 4; jn++) {                      \
            mma_tf32(acc[im][jn], ah[im], bl[jn]);            \
            mma_tf32(acc[im][jn], al[im], bh[jn]);            \
            mma_tf32(acc[im][jn], ah[im], bh[jn]);            \
        }                                                     \
    }                                                         \
    __syncthreads();

// seg_s / seg_c : [128 stacked s-rows] x [1024 p], K = 256 (split-3 tf32, measured 53.5us)
__global__ __launch_bounds__(256, 2) void k_seggemm3(
    const float* __restrict__ seg,
    const float* __restrict__ Ws1, const float* __restrict__ bs1,
    const float* __restrict__ Ws11, const float* __restrict__ bs11) {
    const int n = blockIdx.y;
    const int q0 = blockIdx.x * 128;
    const float* segn = seg + (size_t)n * C_DIM * HW;
    TMMA3_DECL();
    for (int k0 = 0; k0 < C_DIM; k0 += 16) {
        #pragma unroll
        for (int i = 0; i < 8; i++) {
            int e = tid + i * 256, kk = e & 15, m = e >> 4;
            float w = (m < 64) ? Ws1[m * 256 + k0 + kk]
                               : Ws11[(m - 64) * 256 + k0 + kk];
            split_tf32(w, Ah[kk][m], Al[kk][m]);
        }
        #pragma unroll
        for (int i = 0; i < 8; i++) {
            int e = tid + i * 256, kk = e >> 7, j = e & 127;
            split_tf32(segn[(k0 + kk) * HW + q0 + j], Bh[kk][j], Bl[kk][j]);
        }
        TMMA3_COMPUTE();
    }
    #pragma unroll
    for (int im = 0; im < 4; im++) {
        int m = wm + im * 16 + g;
        #pragma unroll
        for (int rr = 0; rr < 2; rr++) {
            int mr = m + rr * 8;
            float bias = (mr < 64) ? bs1[mr] : bs11[mr - 64];
            float* dst = (mr < 64) ? (d_segs + n * S_DIM * HW + mr * HW)
                                   : (d_segc + n * S_DIM * HW + (mr - 64) * HW);
            #pragma unroll
            for (int jn = 0; jn < 4; jn++) {
                int q = q0 + wn + jn * 8 + 2 * tg;
                *(float2*)&dst[q] = make_float2(acc[im][jn][rr * 2] + bias,
                                                acc[im][jn][rr * 2 + 1] + bias);
            }
        }
    }
}

// per-column softmax stats for both branches (online; part of the 841us measurement)
__global__ void k_stats() {
    int n = blockIdx.y;
    int q = blockIdx.x * 256 + threadIdx.x;
    __shared__ float su[HW], se[HW];
    for (int i = threadIdx.x; i < HW; i += 256) {
        su[i] = d_u[n * HW + i];
        se[i] = d_e[n * HW + i];
    }
    __syncthreads();
    float vq = d_v[n * HW + q], mcq = d_mc[n * HW + q], gq = d_g[n * HW + q];
    float Zc = 0.f, ms = -3.0e38f, Zs = 0.f;
    const float* Scol = d_S + (size_t)n * HW * HW + q;
    #pragma unroll 4
    for (int p = 0; p < HW; p++) {
        float s = Scol[(size_t)p * HW];
        Zc += fexp(fmaf(su[p], vq, -mcq));
        float Ls = se[p] * gq * s;
        float mnew = fmaxf(ms, Ls);
        Zs = Zs * fexp(ms - mnew) + fexp(Ls - mnew);
        ms = mnew;
    }
    d_rZc[n * HW + q] = 1.0f / Zc;
    d_ms[n * HW + q]  = ms;
    d_rZs[n * HW + q] = 1.0f / Zs;
}

// similarity = softmax_c + softmax_s, in-place over d_S
__global__ void k_combine() {
    int p = blockIdx.x, n = blockIdx.y;
    float up = d_u[n * HW + p], ep = d_e[n * HW + p];
    float* Srow = d_S + (size_t)(n * HW + p) * HW;
    int base = n * HW;
    for (int j = threadIdx.x; j < HW; j += 256) {
        float s  = Srow[j];
        float lc = fmaf(up, d_v[base + j], -d_mc[base + j]);
        float ls = fmaf(ep * d_g[base + j], s, -d_ms[base + j]);
        Srow[j] = fexp(lc) * d_rZc[base + j] + fexp(ls) * d_rZs[base + j];
    }
}

// ======== cp.async double-buffered tf32 GEMM (raw fp32 bits fed to mma) ========
// A smem: [2][128][20] m-major (conflict-free frags); B smem: [2][16][136]
#define CPMMA_BODY(APTR, ASTRIDE, BPTR, KTOT)                                  \
    __shared__ float As[2][128][20];                                           \
    __shared__ float Bs[2][16][136];                                           \
    TMMA_IDX()                                                                 \
    const int T = (KTOT) / 16;                                                 \
    {                                                                          \
        int k0 = 0;                                                            \
        _Pragma("unroll")                                                      \
        for (int i = 0; i < 2; i++) {                                          \
            int id = tid + i * 256, row = id >> 2, c4 = id & 3;                \
            cp16(&As[0][row][c4 * 4], (APTR) + (size_t)(row) * (ASTRIDE) + k0 + c4 * 4); \
        }                                                                      \
        _Pragma("unroll")                                                      \
        for (int i = 0; i < 2; i++) {                                          \
            int id = tid + i * 256, row = id >> 5, c = id & 31;                \
            cp16(&Bs[0][row][c * 4], (BPTR) + (size_t)(k0 + row) * HW + q0 + c * 4); \
        }                                                                      \
        asm volatile("cp.async.commit_group;");                                \
    }                                                                          \
    for (int t = 0; t < T; t++) {                                              \
        int st = t & 1;                                                        \
        if (t + 1 < T) {                                                       \
            int k0 = (t + 1) * 16;                                             \
            _Pragma("unroll")                                                  \
            for (int i = 0; i < 2; i++) {                                      \
                int id = tid + i * 256, row = id >> 2, c4 = id & 3;            \
                cp16(&As[st ^ 1][row][c4 * 4], (APTR) + (size_t)(row) * (ASTRIDE) + k0 + c4 * 4); \
            }                                                                  \
            _Pragma("unroll")                                                  \
            for (int i = 0; i < 2; i++) {                                      \
                int id = tid + i * 256, row = id >> 5, c = id & 31;            \
                cp16(&Bs[st ^ 1][row][c * 4], (BPTR) + (size_t)(k0 + row) * HW + q0 + c * 4); \
            }                                                                  \
            asm volatile("cp.async.commit_group;");                            \
            asm volatile("cp.async.wait_group 1;");                            \
        } else {                                                               \
            asm volatile("cp.async.wait_group 0;");                            \
        }                                                                      \
        __syncthreads();                                                       \
        _Pragma("unroll")                                                      \
        for (int ks = 0; ks < 16; ks += 8) {                                   \
            uint32_t af[4][4], bfr[4][2];                                      \
            _Pragma("unroll")                                                  \
            for (int im = 0; im < 4; im++) {                                   \
                int mr = wm + im * 16 + g;                                     \
                af[im][0] = __float_as_uint(As[st][mr][ks + tg]);              \
                af[im][1] = __float_as_uint(As[st][mr + 8][ks + tg]);          \
                af[im][2] = __float_as_uint(As[st][mr][ks + tg + 4]);          \
                af[im][3] = __float_as_uint(As[st][mr + 8][ks + tg + 4]);      \
            }                                                                  \
            _Pragma("unroll")                                                  \
            for (int jn = 0; jn < 4; jn++) {                                   \
                int nc = wn + jn * 8 + g;                                      \
                bfr[jn][0] = __float_as_uint(Bs[st][ks + tg][nc]);             \
                bfr[jn][1] = __float_as_uint(Bs[st][ks + tg + 4][nc]);         \
            }                                                                  \
            _Pragma("unroll")                                                  \
            for (int im = 0; im < 4; im++)                                     \
            _Pragma("unroll")                                                  \
            for (int jn = 0; jn < 4; jn++)                                     \
                mma_tf32(acc[im][jn], af[im], bfr[jn]);                        \
        }                                                                      \
        __syncthreads();                                                       \
    }

// seg_sim = seg2 @ similarity
__global__ __launch_bounds__(256, 2) void k_bmm2(const float* __restrict__ seg) {
    const int n = blockIdx.z;
    const int m0 = blockIdx.y * 128, q0 = blockIdx.x * 128;
    const float* A = seg + (size_t)n * C_DIM * HW + (size_t)m0 * HW;
    const float* B = d_S + (size_t)n * HW * HW;
    CPMMA_BODY(A, HW, B, HW);
    float* C = d_segsim + (size_t)n * C_DIM * HW;
    #pragma unroll
    for (int im = 0; im < 4; im++) {
        int m = m0 + wm + im * 16 + g;
        #pragma unroll
        for (int jn = 0; jn < 4; jn++) {
            int q = q0 + wn + jn * 8 + 2 * tg;
            *(float2*)&C[(size_t)m * HW + q]       = make_float2(acc[im][jn][0], acc[im][jn][1]);
            *(float2*)&C[(size_t)(m + 8) * HW + q] = make_float2(acc[im][jn][2], acc[im][jn][3]);
        }
    }
}

// out = relu(W_g @ seg_sim + b_g) + 2*seg
__global__ __launch_bounds__(256, 2) void k_final2(
    const float* __restrict__ Wg, const float* __restrict__ bg,
    const float* __restrict__ seg, float* __restrict__ out) {
    const int n = blockIdx.z;
    const int m0 = blockIdx.y * 128, q0 = blockIdx.x * 128;
    const float* A = Wg + (size_t)m0 * C_DIM;
    const float* B = d_segsim + (size_t)n * C_DIM * HW;
    CPMMA_BODY(A, C_DIM, B, C_DIM);
    const float* segn = seg + (size_t)n * C_DIM * HW;
    float* outn = out + (size_t)n * C_DIM * HW;
    #pragma unroll
    for (int im = 0; im < 4; im++) {
        int m = m0 + wm + im * 16 + g;
        float b0 = bg[m], b1 = bg[m + 8];
        #pragma unroll
        for (int jn = 0; jn < 4; jn++) {
            int q = q0 + wn + jn * 8 + 2 * tg;
            float2 s0 = *(const float2*)&segn[m * HW + q];
            float2 s1 = *(const float2*)&segn[(m + 8) * HW + q];
            float2 r0, r1;
            r0.x = fmaxf(acc[im][jn][0] + b0, 0.f) + 2.f * s0.x;
            r0.y = fmaxf(acc[im][jn][1] + b0, 0.f) + 2.f * s0.y;
            r1.x = fmaxf(acc[im][jn][2] + b1, 0.f) + 2.f * s1.x;
            r1.y = fmaxf(acc[im][jn][3] + b1, 0.f) + 2.f * s1.y;
            *(float2*)&outn[m * HW + q] = r0;
            *(float2*)&outn[(m + 8) * HW + q] = r1;
        }
    }
}

// ---------------- launch ----------------
extern "C" void kernel_launch(void* const* d_in, const int* in_sizes, int n_in,
                              void* d_out, int out_size) {
    const float* seg  = (const float*)d_in[0];
    const float* edge = (const float*)d_in[1];
    const float* Ws1  = (const float*)d_in[2];
    const float* bs1  = (const float*)d_in[3];
    const float* Ws11 = (const float*)d_in[4];
    const float* bs11 = (const float*)d_in[5];
    const float* Wmlp = (const float*)d_in[6];
    const float* bmlp = (const float*)d_in[7];
    const float* ws2  = (const float*)d_in[8];
    const float* bs2  = (const float*)d_in[9];
    const float* ws3  = (const float*)d_in[10];
    const float* bs3  = (const float*)d_in[11];
    const float* Wg   = (const float*)d_in[12];
    const float* bg   = (const float*)d_in[13];
    float* out = (float*)d_out;

    k_mean    <<<N_B * C_DIM, 256>>>(seg);
    k_chatt   <<<N_B, 64>>>(Wmlp, bmlp);
    k_pool    <<<dim3(4, N_B), 256>>>(seg, edge, ws2, bs2, ws3, bs3);
    k_seggemm3<<<dim3(8, N_B), 256>>>(seg, Ws1, bs1, Ws11, bs11);
    k_uv      <<<N_B, 1024>>>();
    k_sgemm   <<<dim3(8, 8, N_B), 256>>>();
    k_stats   <<<dim3(4, N_B), 256>>>();
    k_combine <<<dim3(HW, N_B), 256>>>();
    k_bmm2    <<<dim3(8, 2, N_B), 256>>>(seg);
    k_final2  <<<dim3(8, 2, N_B), 256>>>(Wg, bg, seg, out);
}

// round 15
// speedup vs baseline: 1.3364x; 1.0419x over previous
#include <cuda_runtime.h>
#include <cstdint>

#define N_B   32
#define C_DIM 256
#define HW    1024
#define S_DIM 64

// ---------------- scratch (device globals; no allocations allowed) ----------------
__device__ float d_segs[N_B * S_DIM * HW];     // seg_s  (n, s*hw flat)
__device__ float d_segc[N_B * S_DIM * HW];     // seg_c
__device__ float d_mean[N_B * C_DIM];
__device__ float d_a[N_B * S_DIM];             // ch_att
__device__ float d_u[N_B * HW];
__device__ float d_v[N_B * HW];
__device__ float d_mc[N_B * HW];               // column max, branch c
__device__ float d_e[N_B * HW];                // edge_mm (per p)
__device__ float d_g[N_B * HW];                // seg_ss  (per q)
__device__ float d_rZc[N_B * HW];
__device__ float d_ms[N_B * HW];
__device__ float d_rZs[N_B * HW];
__device__ float d_S[(size_t)N_B * HW * HW];   // sigma_out -> similarity (in-place)
__device__ float d_segsim[N_B * C_DIM * HW];

// ---------------- fast exp on the FMA pipe ----------------
__device__ __forceinline__ float fexp(float x) {
    float z = fmaxf(x * 1.442695041f, -126.0f);
    int   zi = __float2int_rn(z);
    float f  = z - (float)zi;
    float p  = 0.000154035304f;
    p = fmaf(p, f, 0.00133335581f);
    p = fmaf(p, f, 0.00961812910f);
    p = fmaf(p, f, 0.0555041087f);
    p = fmaf(p, f, 0.240226507f);
    p = fmaf(p, f, 0.693147181f);
    p = fmaf(p, f, 1.0f);
    return __int_as_float((zi + 127) << 23) * p;
}

// ---------------- tf32 helpers ----------------
__device__ __forceinline__ uint32_t to_tf32(float x) {
    uint32_t r;
    asm("cvt.rna.tf32.f32 %0, %1;" : "=r"(r) : "f"(x));
    return r;
}
__device__ __forceinline__ void split_tf32(float x, uint32_t& hi, uint32_t& lo) {
    hi = to_tf32(x);
    lo = to_tf32(x - __uint_as_float(hi));
}
__device__ __forceinline__ void mma_tf32(float* c, const uint32_t* a, const uint32_t* b) {
    asm volatile(
        "mma.sync.aligned.m16n8k8.row.col.f32.tf32.tf32.f32 "
        "{%0,%1,%2,%3}, {%4,%5,%6,%7}, {%8,%9}, {%0,%1,%2,%3};"
        : "+f"(c[0]), "+f"(c[1]), "+f"(c[2]), "+f"(c[3])
        : "r"(a[0]), "r"(a[1]), "r"(a[2]), "r"(a[3]), "r"(b[0]), "r"(b[1]));
}
__device__ __forceinline__ void cp16(void* s, const void* g) {
    uint32_t sa = (uint32_t)__cvta_generic_to_shared(s);
    asm volatile("cp.async.cg.shared.global [%0], [%1], 16;" :: "r"(sa), "l"(g));
}

// ---------------- small kernels ----------------
__global__ void k_mean(const float* __restrict__ seg) {
    int n = blockIdx.x >> 8, c = blockIdx.x & 255;
    const float* p = seg + ((size_t)n * C_DIM + c) * HW;
    float s = 0.f;
    for (int i = threadIdx.x; i < HW; i += 256) s += p[i];
    __shared__ float sm[8];
    for (int o = 16; o > 0; o >>= 1) s += __shfl_down_sync(~0u, s, o);
    if ((threadIdx.x & 31) == 0) sm[threadIdx.x >> 5] = s;
    __syncthreads();
    if (threadIdx.x == 0) {
        float t = 0.f;
        #pragma unroll
        for (int i = 0; i < 8; i++) t += sm[i];
        d_mean[n * C_DIM + c] = t * (1.0f / HW);
    }
}

__global__ void k_chatt(const float* __restrict__ Wm, const float* __restrict__ bm) {
    int n = blockIdx.x;
    __shared__ float mn[C_DIM];
    for (int i = threadIdx.x; i < C_DIM; i += 64) mn[i] = d_mean[n * C_DIM + i];
    __syncthreads();
    int s = threadIdx.x;
    float acc = bm[s];
    const float* w = Wm + s * C_DIM;
    #pragma unroll 8
    for (int c = 0; c < C_DIM; c++) acc = fmaf(mn[c], w[c], acc);
    d_a[n * S_DIM + s] = fmaxf(acc, 0.f);
}

__global__ void k_pool(const float* __restrict__ seg, const float* __restrict__ edge,
                       const float* __restrict__ ws2, const float* __restrict__ bs2,
                       const float* __restrict__ ws3, const float* __restrict__ bs3) {
    int p = blockIdx.x * 256 + threadIdx.x;
    int n = blockIdx.y;
    const float* sp = seg  + (size_t)n * C_DIM * HW + p;
    const float* ep = edge + (size_t)n * C_DIM * HW + p;
    float ms = -3.0e38f, me = -3.0e38f;
    #pragma unroll 4
    for (int c = 0; c < C_DIM; c++) {
        float sv = sp[c * HW], ev = ep[c * HW];
        ms = fmaxf(ms, sv);
        me = fmaxf(me, sv * ev);
    }
    d_g[n * HW + p] = ms * ws2[0] + bs2[0];
    d_e[n * HW + p] = me * ws3[0] + bs3[0];
}

__global__ void k_uv() {
    int n = blockIdx.x, t = threadIdx.x;
    __shared__ float sa[S_DIM];
    __shared__ float smax[32], smin[32];
    if (t < S_DIM) sa[t] = d_a[n * S_DIM + t];
    __syncthreads();
    const float* F = d_segs + n * S_DIM * HW;
    float u = 0.f;
    const float* row = F + t * S_DIM;
    #pragma unroll
    for (int k = 0; k < S_DIM; k++) u = fmaf(row[k], sa[k], u);
    d_u[n * HW + t] = u;
    float um = u, un = u;
    for (int o = 16; o > 0; o >>= 1) {
        um = fmaxf(um, __shfl_xor_sync(~0u, um, o));
        un = fminf(un, __shfl_xor_sync(~0u, un, o));
    }
    if ((t & 31) == 0) { smax[t >> 5] = um; smin[t >> 5] = un; }
    __syncthreads();
    if (t < 32) {
        float a1 = smax[t], b1 = smin[t];
        for (int o = 16; o > 0; o >>= 1) {
            a1 = fmaxf(a1, __shfl_xor_sync(~0u, a1, o));
            b1 = fminf(b1, __shfl_xor_sync(~0u, b1, o));
        }
        if (t == 0) { smax[0] = a1; smin[0] = b1; }
    }
    __syncthreads();
    float Umax = smax[0], Umin = smin[0];
    float v = 0.f;
    #pragma unroll
    for (int k = 0; k < S_DIM; k++) v = fmaf(sa[k], F[k * HW + t], v);
    d_v[n * HW + t]  = v;
    d_mc[n * HW + t] = (v >= 0.f) ? v * Umax : v * Umin;
}

// ======== tf32 mma indices (128x128 block, 8 warps @ 64x32) ========
#define TMMA_IDX()                                            \
    const int tid = threadIdx.x;                              \
    const int lane = tid & 31;                                \
    const int wrp = tid >> 5;                                 \
    const int wm = (wrp & 1) * 64;                            \
    const int wn = (wrp >> 1) * 32;                           \
    const int g = lane >> 2, tg = lane & 3;                   \
    float acc[4][4][4];                                       \
    _Pragma("unroll") for (int i_ = 0; i_ < 4; i_++)          \
    _Pragma("unroll") for (int j_ = 0; j_ < 4; j_++)          \
    _Pragma("unroll") for (int r_ = 0; r_ < 4; r_++) acc[i_][j_][r_] = 0.f;

#define TMMA3_DECL()                                          \
    __shared__ uint32_t Ah[16][136], Al[16][136];             \
    __shared__ uint32_t Bh[16][136], Bl[16][136];             \
    TMMA_IDX()

#define TMMA3_COMPUTE()                                       \
    __syncthreads();                                          \
    _Pragma("unroll")                                         \
    for (int ks = 0; ks < 16; ks += 8) {                      \
        uint32_t ah[4][4], al[4][4], bh[4][2], bl[4][2];      \
        _Pragma("unroll")                                     \
        for (int im = 0; im < 4; im++) {                      \
            int mr = wm + im * 16 + g;                        \
            ah[im][0] = Ah[ks + tg][mr];                      \
            ah[im][1] = Ah[ks + tg][mr + 8];                  \
            ah[im][2] = Ah[ks + tg + 4][mr];                  \
            ah[im][3] = Ah[ks + tg + 4][mr + 8];              \
            al[im][0] = Al[ks + tg][mr];                      \
            al[im][1] = Al[ks + tg][mr + 8];                  \
            al[im][2] = Al[ks + tg + 4][mr];                  \
            al[im][3] = Al[ks + tg + 4][mr + 8];              \
        }                                                     \
        _Pragma("unroll")                                     \
        for (int jn = 0; jn < 4; jn++) {                      \
            int nc = wn + jn * 8 + g;                         \
            bh[jn][0] = Bh[ks + tg][nc];                      \
            bh[jn][1] = Bh[ks + tg + 4][nc];                  \
            bl[jn][0] = Bl[ks + tg][nc];                      \
            bl[jn][1] = Bl[ks + tg + 4][nc];                  \
        }                                                     \
        _Pragma("unroll")                                     \
        for (int im = 0; im < 4; im++)                        \
        _Pragma("unroll")                                     \
        for (int jn = 0; jn < 4; jn++) {                      \
            mma_tf32(acc[im][jn], ah[im], bl[jn]);            \
            mma_tf32(acc[im][jn], al[im], bh[jn]);            \
            mma_tf32(acc[im][jn], ah[im], bh[jn]);            \
        }                                                     \
    }                                                         \
    __syncthreads();

// seg_s / seg_c : [128 stacked s-rows] x [1024 p], K = 256 (split-3 tf32, measured 54us)
__global__ __launch_bounds__(256, 2) void k_seggemm3(
    const float* __restrict__ seg,
    const float* __restrict__ Ws1, const float* __restrict__ bs1,
    const float* __restrict__ Ws11, const float* __restrict__ bs11) {
    const int n = blockIdx.y;
    const int q0 = blockIdx.x * 128;
    const float* segn = seg + (size_t)n * C_DIM * HW;
    TMMA3_DECL();
    for (int k0 = 0; k0 < C_DIM; k0 += 16) {
        #pragma unroll
        for (int i = 0; i < 8; i++) {
            int e = tid + i * 256, kk = e & 15, m = e >> 4;
            float w = (m < 64) ? Ws1[m * 256 + k0 + kk]
                               : Ws11[(m - 64) * 256 + k0 + kk];
            split_tf32(w, Ah[kk][m], Al[kk][m]);
        }
        #pragma unroll
        for (int i = 0; i < 8; i++) {
            int e = tid + i * 256, kk = e >> 7, j = e & 127;
            split_tf32(segn[(k0 + kk) * HW + q0 + j], Bh[kk][j], Bl[kk][j]);
        }
        TMMA3_COMPUTE();
    }
    #pragma unroll
    for (int im = 0; im < 4; im++) {
        int m = wm + im * 16 + g;
        #pragma unroll
        for (int rr = 0; rr < 2; rr++) {
            int mr = m + rr * 8;
            float bias = (mr < 64) ? bs1[mr] : bs11[mr - 64];
            float* dst = (mr < 64) ? (d_segs + n * S_DIM * HW + mr * HW)
                                   : (d_segc + n * S_DIM * HW + (mr - 64) * HW);
            #pragma unroll
            for (int jn = 0; jn < 4; jn++) {
                int q = q0 + wn + jn * 8 + 2 * tg;
                *(float2*)&dst[q] = make_float2(acc[im][jn][rr * 2] + bias,
                                                acc[im][jn][rr * 2 + 1] + bias);
            }
        }
    }
}

// sigma_out: split-3 tf32 on the cp.async pipeline.
// A = F rows (p, stride 64), B = F (k-major, stride HW). K=64, ~fp32 accuracy.
__global__ __launch_bounds__(256, 2) void k_sgemm3cp() {
    const int n = blockIdx.z;
    const float* F = d_segc + n * S_DIM * HW;
    const int p0 = blockIdx.y * 128, q0 = blockIdx.x * 128;
    const float* A = F + (size_t)p0 * S_DIM;
    __shared__ float As[2][128][20];
    __shared__ float Bs[2][16][136];
    TMMA_IDX();
    const int T = S_DIM / 16;  // 4
    {
        #pragma unroll
        for (int i = 0; i < 2; i++) {
            int id = tid + i * 256, row = id >> 2, c4 = id & 3;
            cp16(&As[0][row][c4 * 4], A + (size_t)row * S_DIM + c4 * 4);
        }
        #pragma unroll
        for (int i = 0; i < 2; i++) {
            int id = tid + i * 256, row = id >> 5, c = id & 31;
            cp16(&Bs[0][row][c * 4], F + (size_t)row * HW + q0 + c * 4);
        }
        asm volatile("cp.async.commit_group;");
    }
    for (int t = 0; t < T; t++) {
        int st = t & 1;
        if (t + 1 < T) {
            int k0 = (t + 1) * 16;
            #pragma unroll
            for (int i = 0; i < 2; i++) {
                int id = tid + i * 256, row = id >> 2, c4 = id & 3;
                cp16(&As[st ^ 1][row][c4 * 4], A + (size_t)row * S_DIM + k0 + c4 * 4);
            }
            #pragma unroll
            for (int i = 0; i < 2; i++) {
                int id = tid + i * 256, row = id >> 5, c = id & 31;
                cp16(&Bs[st ^ 1][row][c * 4], F + (size_t)(k0 + row) * HW + q0 + c * 4);
            }
            asm volatile("cp.async.commit_group;");
            asm volatile("cp.async.wait_group 1;");
        } else {
            asm volatile("cp.async.wait_group 0;");
        }
        __syncthreads();
        #pragma unroll
        for (int ks = 0; ks < 16; ks += 8) {
            uint32_t ah[4][4], al[4][4], bh[4][2], bl[4][2];
            #pragma unroll
            for (int im = 0; im < 4; im++) {
                int mr = wm + im * 16 + g;
                split_tf32(As[st][mr][ks + tg],         ah[im][0], al[im][0]);
                split_tf32(As[st][mr + 8][ks + tg],     ah[im][1], al[im][1]);
                split_tf32(As[st][mr][ks + tg + 4],     ah[im][2], al[im][2]);
                split_tf32(As[st][mr + 8][ks + tg + 4], ah[im][3], al[im][3]);
            }
            #pragma unroll
            for (int jn = 0; jn < 4; jn++) {
                int nc = wn + jn * 8 + g;
                split_tf32(Bs[st][ks + tg][nc],     bh[jn][0], bl[jn][0]);
                split_tf32(Bs[st][ks + tg + 4][nc], bh[jn][1], bl[jn][1]);
            }
            #pragma unroll
            for (int im = 0; im < 4; im++)
            #pragma unroll
            for (int jn = 0; jn < 4; jn++) {
                mma_tf32(acc[im][jn], ah[im], bl[jn]);
                mma_tf32(acc[im][jn], al[im], bh[jn]);
                mma_tf32(acc[im][jn], ah[im], bh[jn]);
            }
        }
        __syncthreads();
    }
    float* C = d_S + (size_t)n * HW * HW;
    #pragma unroll
    for (int im = 0; im < 4; im++) {
        int m = p0 + wm + im * 16 + g;
        #pragma unroll
        for (int jn = 0; jn < 4; jn++) {
            int q = q0 + wn + jn * 8 + 2 * tg;
            *(float2*)&C[(size_t)m * HW + q]       = make_float2(acc[im][jn][0], acc[im][jn][1]);
            *(float2*)&C[(size_t)(m + 8) * HW + q] = make_float2(acc[im][jn][2], acc[im][jn][3]);
        }
    }
}

// per-column softmax stats for both branches (online; part of the 711us measurement)
__global__ void k_stats() {
    int n = blockIdx.y;
    int q = blockIdx.x * 256 + threadIdx.x;
    __shared__ float su[HW], se[HW];
    for (int i = threadIdx.x; i < HW; i += 256) {
        su[i] = d_u[n * HW + i];
        se[i] = d_e[n * HW + i];
    }
    __syncthreads();
    float vq = d_v[n * HW + q], mcq = d_mc[n * HW + q], gq = d_g[n * HW + q];
    float Zc = 0.f, ms = -3.0e38f, Zs = 0.f;
    const float* Scol = d_S + (size_t)n * HW * HW + q;
    #pragma unroll 4
    for (int p = 0; p < HW; p++) {
        float s = Scol[(size_t)p * HW];
        Zc += fexp(fmaf(su[p], vq, -mcq));
        float Ls = se[p] * gq * s;
        float mnew = fmaxf(ms, Ls);
        Zs = Zs * fexp(ms - mnew) + fexp(Ls - mnew);
        ms = mnew;
    }
    d_rZc[n * HW + q] = 1.0f / Zc;
    d_ms[n * HW + q]  = ms;
    d_rZs[n * HW + q] = 1.0f / Zs;
}

// similarity = softmax_c + softmax_s, in-place over d_S
__global__ void k_combine() {
    int p = blockIdx.x, n = blockIdx.y;
    float up = d_u[n * HW + p], ep = d_e[n * HW + p];
    float* Srow = d_S + (size_t)(n * HW + p) * HW;
    int base = n * HW;
    for (int j = threadIdx.x; j < HW; j += 256) {
        float s  = Srow[j];
        float lc = fmaf(up, d_v[base + j], -d_mc[base + j]);
        float ls = fmaf(ep * d_g[base + j], s, -d_ms[base + j]);
        Srow[j] = fexp(lc) * d_rZc[base + j] + fexp(ls) * d_rZs[base + j];
    }
}

// ======== cp.async double-buffered tf32 GEMM (raw fp32 bits fed to mma) ========
#define CPMMA_BODY(APTR, ASTRIDE, BPTR, KTOT)                                  \
    __shared__ float As[2][128][20];                                           \
    __shared__ float Bs[2][16][136];                                           \
    TMMA_IDX()                                                                 \
    const int T = (KTOT) / 16;                                                 \
    {                                                                          \
        int k0 = 0;                                                            \
        _Pragma("unroll")                                                      \
        for (int i = 0; i < 2; i++) {                                          \
            int id = tid + i * 256, row = id >> 2, c4 = id & 3;                \
            cp16(&As[0][row][c4 * 4], (APTR) + (size_t)(row) * (ASTRIDE) + k0 + c4 * 4); \
        }                                                                      \
        _Pragma("unroll")                                                      \
        for (int i = 0; i < 2; i++) {                                          \
            int id = tid + i * 256, row = id >> 5, c = id & 31;                \
            cp16(&Bs[0][row][c * 4], (BPTR) + (size_t)(k0 + row) * HW + q0 + c * 4); \
        }                                                                      \
        asm volatile("cp.async.commit_group;");                                \
    }                                                                          \
    for (int t = 0; t < T; t++) {                                              \
        int st = t & 1;                                                        \
        if (t + 1 < T) {                                                       \
            int k0 = (t + 1) * 16;                                             \
            _Pragma("unroll")                                                  \
            for (int i = 0; i < 2; i++) {                                      \
                int id = tid + i * 256, row = id >> 2, c4 = id & 3;            \
                cp16(&As[st ^ 1][row][c4 * 4], (APTR) + (size_t)(row) * (ASTRIDE) + k0 + c4 * 4); \
            }                                                                  \
            _Pragma("unroll")                                                  \
            for (int i = 0; i < 2; i++) {                                      \
                int id = tid + i * 256, row = id >> 5, c = id & 31;            \
                cp16(&Bs[st ^ 1][row][c * 4], (BPTR) + (size_t)(k0 + row) * HW + q0 + c * 4); \
            }                                                                  \
            asm volatile("cp.async.commit_group;");                            \
            asm volatile("cp.async.wait_group 1;");                            \
        } else {                                                               \
            asm volatile("cp.async.wait_group 0;");                            \
        }                                                                      \
        __syncthreads();                                                       \
        _Pragma("unroll")                                                      \
        for (int ks = 0; ks < 16; ks += 8) {                                   \
            uint32_t af[4][4], bfr[4][2];                                      \
            _Pragma("unroll")                                                  \
            for (int im = 0; im < 4; im++) {                                   \
                int mr = wm + im * 16 + g;                                     \
                af[im][0] = __float_as_uint(As[st][mr][ks + tg]);              \
                af[im][1] = __float_as_uint(As[st][mr + 8][ks + tg]);          \
                af[im][2] = __float_as_uint(As[st][mr][ks + tg + 4]);          \
                af[im][3] = __float_as_uint(As[st][mr + 8][ks + tg + 4]);      \
            }                                                                  \
            _Pragma("unroll")                                                  \
            for (int jn = 0; jn < 4; jn++) {                                   \
                int nc = wn + jn * 8 + g;                                      \
                bfr[jn][0] = __float_as_uint(Bs[st][ks + tg][nc]);             \
                bfr[jn][1] = __float_as_uint(Bs[st][ks + tg + 4][nc]);         \
            }                                                                  \
            _Pragma("unroll")                                                  \
            for (int im = 0; im < 4; im++)                                     \
            _Pragma("unroll")                                                  \
            for (int jn = 0; jn < 4; jn++)                                     \
                mma_tf32(acc[im][jn], af[im], bfr[jn]);                        \
        }                                                                      \
        __syncthreads();                                                       \
    }

// seg_sim = seg2 @ similarity
__global__ __launch_bounds__(256, 2) void k_bmm2(const float* __restrict__ seg) {
    const int n = blockIdx.z;
    const int m0 = blockIdx.y * 128, q0 = blockIdx.x * 128;
    const float* A = seg + (size_t)n * C_DIM * HW + (size_t)m0 * HW;
    const float* B = d_S + (size_t)n * HW * HW;
    CPMMA_BODY(A, HW, B, HW);
    float* C = d_segsim + (size_t)n * C_DIM * HW;
    #pragma unroll
    for (int im = 0; im < 4; im++) {
        int m = m0 + wm + im * 16 + g;
        #pragma unroll
        for (int jn = 0; jn < 4; jn++) {
            int q = q0 + wn + jn * 8 + 2 * tg;
            *(float2*)&C[(size_t)m * HW + q]       = make_float2(acc[im][jn][0], acc[im][jn][1]);
            *(float2*)&C[(size_t)(m + 8) * HW + q] = make_float2(acc[im][jn][2], acc[im][jn][3]);
        }
    }
}

// out = relu(W_g @ seg_sim + b_g) + 2*seg
__global__ __launch_bounds__(256, 2) void k_final2(
    const float* __restrict__ Wg, const float* __restrict__ bg,
    const float* __restrict__ seg, float* __restrict__ out) {
    const int n = blockIdx.z;
    const int m0 = blockIdx.y * 128, q0 = blockIdx.x * 128;
    const float* A = Wg + (size_t)m0 * C_DIM;
    const float* B = d_segsim + (size_t)n * C_DIM * HW;
    CPMMA_BODY(A, C_DIM, B, C_DIM);
    const float* segn = seg + (size_t)n * C_DIM * HW;
    float* outn = out + (size_t)n * C_DIM * HW;
    #pragma unroll
    for (int im = 0; im < 4; im++) {
        int m = m0 + wm + im * 16 + g;
        float b0 = bg[m], b1 = bg[m + 8];
        #pragma unroll
        for (int jn = 0; jn < 4; jn++) {
            int q = q0 + wn + jn * 8 + 2 * tg;
            float2 s0 = *(const float2*)&segn[m * HW + q];
            float2 s1 = *(const float2*)&segn[(m + 8) * HW + q];
            float2 r0, r1;
            r0.x = fmaxf(acc[im][jn][0] + b0, 0.f) + 2.f * s0.x;
            r0.y = fmaxf(acc[im][jn][1] + b0, 0.f) + 2.f * s0.y;
            r1.x = fmaxf(acc[im][jn][2] + b1, 0.f) + 2.f * s1.x;
            r1.y = fmaxf(acc[im][jn][3] + b1, 0.f) + 2.f * s1.y;
            *(float2*)&outn[m * HW + q] = r0;
            *(float2*)&outn[(m + 8) * HW + q] = r1;
        }
    }
}

// ---------------- launch ----------------
extern "C" void kernel_launch(void* const* d_in, const int* in_sizes, int n_in,
                              void* d_out, int out_size) {
    const float* seg  = (const float*)d_in[0];
    const float* edge = (const float*)d_in[1];
    const float* Ws1  = (const float*)d_in[2];
    const float* bs1  = (const float*)d_in[3];
    const float* Ws11 = (const float*)d_in[4];
    const float* bs11 = (const float*)d_in[5];
    const float* Wmlp = (const float*)d_in[6];
    const float* bmlp = (const float*)d_in[7];
    const float* ws2  = (const float*)d_in[8];
    const float* bs2  = (const float*)d_in[9];
    const float* ws3  = (const float*)d_in[10];
    const float* bs3  = (const float*)d_in[11];
    const float* Wg   = (const float*)d_in[12];
    const float* bg   = (const float*)d_in[13];
    float* out = (float*)d_out;

    k_mean    <<<N_B * C_DIM, 256>>>(seg);
    k_chatt   <<<N_B, 64>>>(Wmlp, bmlp);
    k_pool    <<<dim3(4, N_B), 256>>>(seg, edge, ws2, bs2, ws3, bs3);
    k_seggemm3<<<dim3(8, N_B), 256>>>(seg, Ws1, bs1, Ws11, bs11);
    k_uv      <<<N_B, 1024>>>();
    k_sgemm3cp<<<dim3(8, 8, N_B), 256>>>();
    k_stats   <<<dim3(4, N_B), 256>>>();
    k_combine <<<dim3(HW, N_B), 256>>>();
    k_bmm2    <<<dim3(8, 2, N_B), 256>>>(seg);
    k_final2  <<<dim3(8, 2, N_B), 256>>>(Wg, bg, seg, out);
}

// round 17
// speedup vs baseline: 1.3561x; 1.0148x over previous
#include <cuda_runtime.h>
#include <cstdint>

#define N_B   32
#define C_DIM 256
#define HW    1024
#define S_DIM 64

// ---------------- scratch (device globals; no allocations allowed) ----------------
__device__ float d_segs[N_B * S_DIM * HW];     // seg_s  (n, s*hw flat)
__device__ float d_segc[N_B * S_DIM * HW];     // seg_c
__device__ float d_mean[N_B * C_DIM];
__device__ float d_a[N_B * S_DIM];             // ch_att
__device__ float d_u[N_B * HW];
__device__ float d_v[N_B * HW];
__device__ float d_mc[N_B * HW];               // column max, branch c
__device__ float d_e[N_B * HW];                // edge_mm (per p)
__device__ float d_g[N_B * HW];                // seg_ss  (per q)
__device__ float d_rZc[N_B * HW];
__device__ float d_ms[N_B * HW];
__device__ float d_rZs[N_B * HW];
__device__ float d_S[(size_t)N_B * HW * HW];   // raw sigma_out (never overwritten now)
__device__ float d_segsim[N_B * C_DIM * HW];

// ---------------- fast exp on the FMA pipe (serial-chain use only) ----------------
__device__ __forceinline__ float fexp(float x) {
    float z = fmaxf(x * 1.442695041f, -126.0f);
    int   zi = __float2int_rn(z);
    float f  = z - (float)zi;
    float p  = 0.000154035304f;
    p = fmaf(p, f, 0.00133335581f);
    p = fmaf(p, f, 0.00961812910f);
    p = fmaf(p, f, 0.0555041087f);
    p = fmaf(p, f, 0.240226507f);
    p = fmaf(p, f, 0.693147181f);
    p = fmaf(p, f, 1.0f);
    return __int_as_float((zi + 127) << 23) * p;
}

// ---------------- tf32 helpers ----------------
__device__ __forceinline__ uint32_t to_tf32(float x) {
    uint32_t r;
    asm("cvt.rna.tf32.f32 %0, %1;" : "=r"(r) : "f"(x));
    return r;
}
__device__ __forceinline__ void split_tf32(float x, uint32_t& hi, uint32_t& lo) {
    hi = to_tf32(x);
    lo = to_tf32(x - __uint_as_float(hi));
}
__device__ __forceinline__ void mma_tf32(float* c, const uint32_t* a, const uint32_t* b) {
    asm volatile(
        "mma.sync.aligned.m16n8k8.row.col.f32.tf32.tf32.f32 "
        "{%0,%1,%2,%3}, {%4,%5,%6,%7}, {%8,%9}, {%0,%1,%2,%3};"
        : "+f"(c[0]), "+f"(c[1]), "+f"(c[2]), "+f"(c[3])
        : "r"(a[0]), "r"(a[1]), "r"(a[2]), "r"(a[3]), "r"(b[0]), "r"(b[1]));
}
__device__ __forceinline__ void cp16(void* s, const void* g) {
    uint32_t sa = (uint32_t)__cvta_generic_to_shared(s);
    asm volatile("cp.async.cg.shared.global [%0], [%1], 16;" :: "r"(sa), "l"(g));
}

// ---------------- small kernels ----------------
__global__ void k_mean(const float* __restrict__ seg) {
    int n = blockIdx.x >> 8, c = blockIdx.x & 255;
    const float* p = seg + ((size_t)n * C_DIM + c) * HW;
    float s = 0.f;
    for (int i = threadIdx.x; i < HW; i += 256) s += p[i];
    __shared__ float sm[8];
    for (int o = 16; o > 0; o >>= 1) s += __shfl_down_sync(~0u, s, o);
    if ((threadIdx.x & 31) == 0) sm[threadIdx.x >> 5] = s;
    __syncthreads();
    if (threadIdx.x == 0) {
        float t = 0.f;
        #pragma unroll
        for (int i = 0; i < 8; i++) t += sm[i];
        d_mean[n * C_DIM + c] = t * (1.0f / HW);
    }
}

__global__ void k_chatt(const float* __restrict__ Wm, const float* __restrict__ bm) {
    int n = blockIdx.x;
    __shared__ float mn[C_DIM];
    for (int i = threadIdx.x; i < C_DIM; i += 64) mn[i] = d_mean[n * C_DIM + i];
    __syncthreads();
    int s = threadIdx.x;
    float acc = bm[s];
    const float* w = Wm + s * C_DIM;
    #pragma unroll 8
    for (int c = 0; c < C_DIM; c++) acc = fmaf(mn[c], w[c], acc);
    d_a[n * S_DIM + s] = fmaxf(acc, 0.f);
}

__global__ void k_pool(const float* __restrict__ seg, const float* __restrict__ edge,
                       const float* __restrict__ ws2, const float* __restrict__ bs2,
                       const float* __restrict__ ws3, const float* __restrict__ bs3) {
    int p = blockIdx.x * 256 + threadIdx.x;
    int n = blockIdx.y;
    const float* sp = seg  + (size_t)n * C_DIM * HW + p;
    const float* ep = edge + (size_t)n * C_DIM * HW + p;
    float ms = -3.0e38f, me = -3.0e38f;
    #pragma unroll 4
    for (int c = 0; c < C_DIM; c++) {
        float sv = sp[c * HW], ev = ep[c * HW];
        ms = fmaxf(ms, sv);
        me = fmaxf(me, sv * ev);
    }
    d_g[n * HW + p] = ms * ws2[0] + bs2[0];
    d_e[n * HW + p] = me * ws3[0] + bs3[0];
}

__global__ void k_uv() {
    int n = blockIdx.x, t = threadIdx.x;
    __shared__ float sa[S_DIM];
    __shared__ float smax[32], smin[32];
    if (t < S_DIM) sa[t] = d_a[n * S_DIM + t];
    __syncthreads();
    const float* F = d_segs + n * S_DIM * HW;
    float u = 0.f;
    const float* row = F + t * S_DIM;
    #pragma unroll
    for (int k = 0; k < S_DIM; k++) u = fmaf(row[k], sa[k], u);
    d_u[n * HW + t] = u;
    float um = u, un = u;
    for (int o = 16; o > 0; o >>= 1) {
        um = fmaxf(um, __shfl_xor_sync(~0u, um, o));
        un = fminf(un, __shfl_xor_sync(~0u, un, o));
    }
    if ((t & 31) == 0) { smax[t >> 5] = um; smin[t >> 5] = un; }
    __syncthreads();
    if (t < 32) {
        float a1 = smax[t], b1 = smin[t];
        for (int o = 16; o > 0; o >>= 1) {
            a1 = fmaxf(a1, __shfl_xor_sync(~0u, a1, o));
            b1 = fminf(b1, __shfl_xor_sync(~0u, b1, o));
        }
        if (t == 0) { smax[0] = a1; smin[0] = b1; }
    }
    __syncthreads();
    float Umax = smax[0], Umin = smin[0];
    float v = 0.f;
    #pragma unroll
    for (int k = 0; k < S_DIM; k++) v = fmaf(sa[k], F[k * HW + t], v);
    d_v[n * HW + t]  = v;
    d_mc[n * HW + t] = (v >= 0.f) ? v * Umax : v * Umin;
}

// ======== tf32 mma indices (128x128 block, 8 warps @ 64x32) ========
#define TMMA_IDX()                                            \
    const int tid = threadIdx.x;                              \
    const int lane = tid & 31;                                \
    const int wrp = tid >> 5;                                 \
    const int wm = (wrp & 1) * 64;                            \
    const int wn = (wrp >> 1) * 32;                           \
    const int g = lane >> 2, tg = lane & 3;                   \
    float acc[4][4][4];                                       \
    _Pragma("unroll") for (int i_ = 0; i_ < 4; i_++)          \
    _Pragma("unroll") for (int j_ = 0; j_ < 4; j_++)          \
    _Pragma("unroll") for (int r_ = 0; r_ < 4; r_++) acc[i_][j_][r_] = 0.f;

#define TMMA3_DECL()                                          \
    __shared__ uint32_t Ah[16][136], Al[16][136];             \
    __shared__ uint32_t Bh[16][136], Bl[16][136];             \
    TMMA_IDX()

#define TMMA3_COMPUTE()                                       \
    __syncthreads();                                          \
    _Pragma("unroll")                                         \
    for (int ks = 0; ks < 16; ks += 8) {                      \
        uint32_t ah[4][4], al[4][4], bh[4][2], bl[4][2];      \
        _Pragma("unroll")                                     \
        for (int im = 0; im < 4; im++) {                      \
            int mr = wm + im * 16 + g;                        \
            ah[im][0] = Ah[ks + tg][mr];                      \
            ah[im][1] = Ah[ks + tg][mr + 8];                  \
            ah[im][2] = Ah[ks + tg + 4][mr];                  \
            ah[im][3] = Ah[ks + tg + 4][mr + 8];              \
            al[im][0] = Al[ks + tg][mr];                      \
            al[im][1] = Al[ks + tg][mr + 8];                  \
            al[im][2] = Al[ks + tg + 4][mr];                  \
            al[im][3] = Al[ks + tg + 4][mr + 8];              \
        }                                                     \
        _Pragma("unroll")                                     \
        for (int jn = 0; jn < 4; jn++) {                      \
            int nc = wn + jn * 8 + g;                         \
            bh[jn][0] = Bh[ks + tg][nc];                      \
            bh[jn][1] = Bh[ks + tg + 4][nc];                  \
            bl[jn][0] = Bl[ks + tg][nc];                      \
            bl[jn][1] = Bl[ks + tg + 4][nc];                  \
        }                                                     \
        _Pragma("unroll")                                     \
        for (int im = 0; im < 4; im++)                        \
        _Pragma("unroll")                                     \
        for (int jn = 0; jn < 4; jn++) {                      \
            mma_tf32(acc[im][jn], ah[im], bl[jn]);            \
            mma_tf32(acc[im][jn], al[im], bh[jn]);            \
            mma_tf32(acc[im][jn], ah[im], bh[jn]);            \
        }                                                     \
    }                                                         \
    __syncthreads();

// seg_s / seg_c : [128 stacked s-rows] x [1024 p], K = 256 (split-3 tf32, measured 54us)
__global__ __launch_bounds__(256, 2) void k_seggemm3(
    const float* __restrict__ seg,
    const float* __restrict__ Ws1, const float* __restrict__ bs1,
    const float* __restrict__ Ws11, const float* __restrict__ bs11) {
    const int n = blockIdx.y;
    const int q0 = blockIdx.x * 128;
    const float* segn = seg + (size_t)n * C_DIM * HW;
    TMMA3_DECL();
    for (int k0 = 0; k0 < C_DIM; k0 += 16) {
        #pragma unroll
        for (int i = 0; i < 8; i++) {
            int e = tid + i * 256, kk = e & 15, m = e >> 4;
            float w = (m < 64) ? Ws1[m * 256 + k0 + kk]
                               : Ws11[(m - 64) * 256 + k0 + kk];
            split_tf32(w, Ah[kk][m], Al[kk][m]);
        }
        #pragma unroll
        for (int i = 0; i < 8; i++) {
            int e = tid + i * 256, kk = e >> 7, j = e & 127;
            split_tf32(segn[(k0 + kk) * HW + q0 + j], Bh[kk][j], Bl[kk][j]);
        }
        TMMA3_COMPUTE();
    }
    #pragma unroll
    for (int im = 0; im < 4; im++) {
        int m = wm + im * 16 + g;
        #pragma unroll
        for (int rr = 0; rr < 2; rr++) {
            int mr = m + rr * 8;
            float bias = (mr < 64) ? bs1[mr] : bs11[mr - 64];
            float* dst = (mr < 64) ? (d_segs + n * S_DIM * HW + mr * HW)
                                   : (d_segc + n * S_DIM * HW + (mr - 64) * HW);
            #pragma unroll
            for (int jn = 0; jn < 4; jn++) {
                int q = q0 + wn + jn * 8 + 2 * tg;
                *(float2*)&dst[q] = make_float2(acc[im][jn][rr * 2] + bias,
                                                acc[im][jn][rr * 2 + 1] + bias);
            }
        }
    }
}

// sigma_out: split-3 tf32 on the cp.async pipeline (measured as part of 682us).
__global__ __launch_bounds__(256, 2) void k_sgemm3cp() {
    const int n = blockIdx.z;
    const float* F = d_segc + n * S_DIM * HW;
    const int p0 = blockIdx.y * 128, q0 = blockIdx.x * 128;
    const float* A = F + (size_t)p0 * S_DIM;
    __shared__ float As[2][128][20];
    __shared__ float Bs[2][16][136];
    TMMA_IDX();
    const int T = S_DIM / 16;  // 4
    {
        #pragma unroll
        for (int i = 0; i < 2; i++) {
            int id = tid + i * 256, row = id >> 2, c4 = id & 3;
            cp16(&As[0][row][c4 * 4], A + (size_t)row * S_DIM + c4 * 4);
        }
        #pragma unroll
        for (int i = 0; i < 2; i++) {
            int id = tid + i * 256, row = id >> 5, c = id & 31;
            cp16(&Bs[0][row][c * 4], F + (size_t)row * HW + q0 + c * 4);
        }
        asm volatile("cp.async.commit_group;");
    }
    for (int t = 0; t < T; t++) {
        int st = t & 1;
        if (t + 1 < T) {
            int k0 = (t + 1) * 16;
            #pragma unroll
            for (int i = 0; i < 2; i++) {
                int id = tid + i * 256, row = id >> 2, c4 = id & 3;
                cp16(&As[st ^ 1][row][c4 * 4], A + (size_t)row * S_DIM + k0 + c4 * 4);
            }
            #pragma unroll
            for (int i = 0; i < 2; i++) {
                int id = tid + i * 256, row = id >> 5, c = id & 31;
                cp16(&Bs[st ^ 1][row][c * 4], F + (size_t)(k0 + row) * HW + q0 + c * 4);
            }
            asm volatile("cp.async.commit_group;");
            asm volatile("cp.async.wait_group 1;");
        } else {
            asm volatile("cp.async.wait_group 0;");
        }
        __syncthreads();
        #pragma unroll
        for (int ks = 0; ks < 16; ks += 8) {
            uint32_t ah[4][4], al[4][4], bh[4][2], bl[4][2];
            #pragma unroll
            for (int im = 0; im < 4; im++) {
                int mr = wm + im * 16 + g;
                split_tf32(As[st][mr][ks + tg],         ah[im][0], al[im][0]);
                split_tf32(As[st][mr + 8][ks + tg],     ah[im][1], al[im][1]);
                split_tf32(As[st][mr][ks + tg + 4],     ah[im][2], al[im][2]);
                split_tf32(As[st][mr + 8][ks + tg + 4], ah[im][3], al[im][3]);
            }
            #pragma unroll
            for (int jn = 0; jn < 4; jn++) {
                int nc = wn + jn * 8 + g;
                split_tf32(Bs[st][ks + tg][nc],     bh[jn][0], bl[jn][0]);
                split_tf32(Bs[st][ks + tg + 4][nc], bh[jn][1], bl[jn][1]);
            }
            #pragma unroll
            for (int im = 0; im < 4; im++)
            #pragma unroll
            for (int jn = 0; jn < 4; jn++) {
                mma_tf32(acc[im][jn], ah[im], bl[jn]);
                mma_tf32(acc[im][jn], al[im], bh[jn]);
                mma_tf32(acc[im][jn], ah[im], bh[jn]);
            }
        }
        __syncthreads();
    }
    float* C = d_S + (size_t)n * HW * HW;
    #pragma unroll
    for (int im = 0; im < 4; im++) {
        int m = p0 + wm + im * 16 + g;
        #pragma unroll
        for (int jn = 0; jn < 4; jn++) {
            int q = q0 + wn + jn * 8 + 2 * tg;
            *(float2*)&C[(size_t)m * HW + q]       = make_float2(acc[im][jn][0], acc[im][jn][1]);
            *(float2*)&C[(size_t)(m + 8) * HW + q] = make_float2(acc[im][jn][2], acc[im][jn][3]);
        }
    }
}

// per-column softmax stats for both branches (online; proven)
__global__ void k_stats() {
    int n = blockIdx.y;
    int q = blockIdx.x * 256 + threadIdx.x;
    __shared__ float su[HW], se[HW];
    for (int i = threadIdx.x; i < HW; i += 256) {
        su[i] = d_u[n * HW + i];
        se[i] = d_e[n * HW + i];
    }
    __syncthreads();
    float vq = d_v[n * HW + q], mcq = d_mc[n * HW + q], gq = d_g[n * HW + q];
    float Zc = 0.f, ms = -3.0e38f, Zs = 0.f;
    const float* Scol = d_S + (size_t)n * HW * HW + q;
    #pragma unroll 4
    for (int p = 0; p < HW; p++) {
        float s = Scol[(size_t)p * HW];
        Zc += fexp(fmaf(su[p], vq, -mcq));
        float Ls = se[p] * gq * s;
        float mnew = fmaxf(ms, Ls);
        Zs = Zs * fexp(ms - mnew) + fexp(Ls - mnew);
        ms = mnew;
    }
    d_rZc[n * HW + q] = 1.0f / Zc;
    d_ms[n * HW + q]  = ms;
    d_rZs[n * HW + q] = 1.0f / Zs;
}

// seg_sim = seg2 @ (softmax_c + softmax_s) — combine fused in-smem, MUFU exp,
// raw sigma read from d_S (no combine kernel, no d_S write-back).
__global__ __launch_bounds__(256, 2) void k_bmm3(const float* __restrict__ seg) {
    const int n = blockIdx.z;
    const int m0 = blockIdx.y * 128, q0 = blockIdx.x * 128;
    const float* A = seg + (size_t)n * C_DIM * HW + (size_t)m0 * HW;
    const float* B = d_S + (size_t)n * HW * HW;
    __shared__ float As[2][128][20];
    __shared__ float Bs[2][16][136];
    __shared__ float su[HW], se[HW];
    TMMA_IDX();
    // per-thread fixed column constants (col = tid & 127)
    const int col = tid & 127;
    const int rsel = tid >> 7;           // 0 or 1
    const int base = n * HW + q0 + col;
    const float cvq  = d_v[base];
    const float cmc  = d_mc[base];
    const float cgq  = d_g[base];
    const float cms  = d_ms[base];
    const float crZc = d_rZc[base];
    const float crZs = d_rZs[base];

    const int T = HW / 16;
    {
        #pragma unroll
        for (int i = 0; i < 2; i++) {
            int id = tid + i * 256, row = id >> 2, c4 = id & 3;
            cp16(&As[0][row][c4 * 4], A + (size_t)row * HW + c4 * 4);
        }
        #pragma unroll
        for (int i = 0; i < 2; i++) {
            int id = tid + i * 256, row = id >> 5, c = id & 31;
            cp16(&Bs[0][row][c * 4], B + (size_t)row * HW + q0 + c * 4);
        }
        asm volatile("cp.async.commit_group;");
        // overlap row-constant preload with the first TMA-less cp.async stage
        for (int i = tid; i < HW; i += 256) {
            su[i] = d_u[n * HW + i];
            se[i] = d_e[n * HW + i];
        }
    }
    for (int t = 0; t < T; t++) {
        int st = t & 1;
        if (t + 1 < T) {
            int k0 = (t + 1) * 16;
            #pragma unroll
            for (int i = 0; i < 2; i++) {
                int id = tid + i * 256, row = id >> 2, c4 = id & 3;
                cp16(&As[st ^ 1][row][c4 * 4], A + (size_t)row * HW + k0 + c4 * 4);
            }
            #pragma unroll
            for (int i = 0; i < 2; i++) {
                int id = tid + i * 256, row = id >> 5, c = id & 31;
                cp16(&Bs[st ^ 1][row][c * 4], B + (size_t)(k0 + row) * HW + q0 + c * 4);
            }
            asm volatile("cp.async.commit_group;");
            asm volatile("cp.async.wait_group 1;");
        } else {
            asm volatile("cp.async.wait_group 0;");
        }
        __syncthreads();
        // combine transform, in-smem (each thread owns 8 elements at fixed col)
        {
            const int k0t = t * 16;
            #pragma unroll
            for (int i = 0; i < 8; i++) {
                int row = i * 2 + rsel;
                int p = k0t + row;
                float s = Bs[st][row][col];
                float val = __expf(fmaf(su[p], cvq, -cmc)) * crZc
                          + __expf(fmaf(se[p] * cgq, s, -cms)) * crZs;
                Bs[st][row][col] = val;
            }
        }
        __syncthreads();
        #pragma unroll
        for (int ks = 0; ks < 16; ks += 8) {
            uint32_t af[4][4], bfr[4][2];
            #pragma unroll
            for (int im = 0; im < 4; im++) {
                int mr = wm + im * 16 + g;
                af[im][0] = __float_as_uint(As[st][mr][ks + tg]);
                af[im][1] = __float_as_uint(As[st][mr + 8][ks + tg]);
                af[im][2] = __float_as_uint(As[st][mr][ks + tg + 4]);
                af[im][3] = __float_as_uint(As[st][mr + 8][ks + tg + 4]);
            }
            #pragma unroll
            for (int jn = 0; jn < 4; jn++) {
                int nc = wn + jn * 8 + g;
                bfr[jn][0] = __float_as_uint(Bs[st][ks + tg][nc]);
                bfr[jn][1] = __float_as_uint(Bs[st][ks + tg + 4][nc]);
            }
            #pragma unroll
            for (int im = 0; im < 4; im++)
            #pragma unroll
            for (int jn = 0; jn < 4; jn++)
                mma_tf32(acc[im][jn], af[im], bfr[jn]);
        }
        __syncthreads();
    }
    float* C = d_segsim + (size_t)n * C_DIM * HW;
    #pragma unroll
    for (int im = 0; im < 4; im++) {
        int m = m0 + wm + im * 16 + g;
        #pragma unroll
        for (int jn = 0; jn < 4; jn++) {
            int q = q0 + wn + jn * 8 + 2 * tg;
            *(float2*)&C[(size_t)m * HW + q]       = make_float2(acc[im][jn][0], acc[im][jn][1]);
            *(float2*)&C[(size_t)(m + 8) * HW + q] = make_float2(acc[im][jn][2], acc[im][jn][3]);
        }
    }
}

// ======== cp.async double-buffered tf32 GEMM (raw fp32 bits fed to mma) ========
#define CPMMA_BODY(APTR, ASTRIDE, BPTR, KTOT)                                  \
    __shared__ float As[2][128][20];                                           \
    __shared__ float Bs[2][16][136];                                           \
    TMMA_IDX()                                                                 \
    const int T = (KTOT) / 16;                                                 \
    {                                                                          \
        int k0 = 0;                                                            \
        _Pragma("unroll")                                                      \
        for (int i = 0; i < 2; i++) {                                          \
            int id = tid + i * 256, row = id >> 2, c4 = id & 3;                \
            cp16(&As[0][row][c4 * 4], (APTR) + (size_t)(row) * (ASTRIDE) + k0 + c4 * 4); \
        }                                                                      \
        _Pragma("unroll")                                                      \
        for (int i = 0; i < 2; i++) {                                          \
            int id = tid + i * 256, row = id >> 5, c = id & 31;                \
            cp16(&Bs[0][row][c * 4], (BPTR) + (size_t)(k0 + row) * HW + q0 + c * 4); \
        }                                                                      \
        asm volatile("cp.async.commit_group;");                                \
    }                                                                          \
    for (int t = 0; t < T; t++) {                                              \
        int st = t & 1;                                                        \
        if (t + 1 < T) {                                                       \
            int k0 = (t + 1) * 16;                                             \
            _Pragma("unroll")                                                  \
            for (int i = 0; i < 2; i++) {                                      \
                int id = tid + i * 256, row = id >> 2, c4 = id & 3;            \
                cp16(&As[st ^ 1][row][c4 * 4], (APTR) + (size_t)(row) * (ASTRIDE) + k0 + c4 * 4); \
            }                                                                  \
            _Pragma("unroll")                                                  \
            for (int i = 0; i < 2; i++) {                                      \
                int id = tid + i * 256, row = id >> 5, c = id & 31;            \
                cp16(&Bs[st ^ 1][row][c * 4], (BPTR) + (size_t)(k0 + row) * HW + q0 + c * 4); \
            }                                                                  \
            asm volatile("cp.async.commit_group;");                            \
            asm volatile("cp.async.wait_group 1;");                            \
        } else {                                                               \
            asm volatile("cp.async.wait_group 0;");                            \
        }                                                                      \
        __syncthreads();                                                       \
        _Pragma("unroll")                                                      \
        for (int ks = 0; ks < 16; ks += 8) {                                   \
            uint32_t af[4][4], bfr[4][2];                                      \
            _Pragma("unroll")                                                  \
            for (int im = 0; im < 4; im++) {                                   \
                int mr = wm + im * 16 + g;                                     \
                af[im][0] = __float_as_uint(As[st][mr][ks + tg]);              \
                af[im][1] = __float_as_uint(As[st][mr + 8][ks + tg]);          \
                af[im][2] = __float_as_uint(As[st][mr][ks + tg + 4]);          \
                af[im][3] = __float_as_uint(As[st][mr + 8][ks + tg + 4]);      \
            }                                                                  \
            _Pragma("unroll")                                                  \
            for (int jn = 0; jn < 4; jn++) {                                   \
                int nc = wn + jn * 8 + g;                                      \
                bfr[jn][0] = __float_as_uint(Bs[st][ks + tg][nc]);             \
                bfr[jn][1] = __float_as_uint(Bs[st][ks + tg + 4][nc]);         \
            }                                                                  \
            _Pragma("unroll")                                                  \
            for (int im = 0; im < 4; im++)                                     \
            _Pragma("unroll")                                                  \
            for (int jn = 0; jn < 4; jn++)                                     \
                mma_tf32(acc[im][jn], af[im], bfr[jn]);                        \
        }                                                                      \
        __syncthreads();                                                       \
    }

// out = relu(W_g @ seg_sim + b_g) + 2*seg
__global__ __launch_bounds__(256, 2) void k_final2(
    const float* __restrict__ Wg, const float* __restrict__ bg,
    const float* __restrict__ seg, float* __restrict__ out) {
    const int n = blockIdx.z;
    const int m0 = blockIdx.y * 128, q0 = blockIdx.x * 128;
    const float* A = Wg + (size_t)m0 * C_DIM;
    const float* B = d_segsim + (size_t)n * C_DIM * HW;
    CPMMA_BODY(A, C_DIM, B, C_DIM);
    const float* segn = seg + (size_t)n * C_DIM * HW;
    float* outn = out + (size_t)n * C_DIM * HW;
    #pragma unroll
    for (int im = 0; im < 4; im++) {
        int m = m0 + wm + im * 16 + g;
        float b0 = bg[m], b1 = bg[m + 8];
        #pragma unroll
        for (int jn = 0; jn < 4; jn++) {
            int q = q0 + wn + jn * 8 + 2 * tg;
            float2 s0 = *(const float2*)&segn[m * HW + q];
            float2 s1 = *(const float2*)&segn[(m + 8) * HW + q];
            float2 r0, r1;
            r0.x = fmaxf(acc[im][jn][0] + b0, 0.f) + 2.f * s0.x;
            r0.y = fmaxf(acc[im][jn][1] + b0, 0.f) + 2.f * s0.y;
            r1.x = fmaxf(acc[im][jn][2] + b1, 0.f) + 2.f * s1.x;
            r1.y = fmaxf(acc[im][jn][3] + b1, 0.f) + 2.f * s1.y;
            *(float2*)&outn[m * HW + q] = r0;
            *(float2*)&outn[(m + 8) * HW + q] = r1;
        }
    }
}

// ---------------- launch ----------------
extern "C" void kernel_launch(void* const* d_in, const int* in_sizes, int n_in,
                              void* d_out, int out_size) {
    const float* seg  = (const float*)d_in[0];
    const float* edge = (const float*)d_in[1];
    const float* Ws1  = (const float*)d_in[2];
    const float* bs1  = (const float*)d_in[3];
    const float* Ws11 = (const float*)d_in[4];
    const float* bs11 = (const float*)d_in[5];
    const float* Wmlp = (const float*)d_in[6];
    const float* bmlp = (const float*)d_in[7];
    const float* ws2  = (const float*)d_in[8];
    const float* bs2  = (const float*)d_in[9];
    const float* ws3  = (const float*)d_in[10];
    const float* bs3  = (const float*)d_in[11];
    const float* Wg   = (const float*)d_in[12];
    const float* bg   = (const float*)d_in[13];
    float* out = (float*)d_out;

    k_mean    <<<N_B * C_DIM, 256>>>(seg);
    k_chatt   <<<N_B, 64>>>(Wmlp, bmlp);
    k_pool    <<<dim3(4, N_B), 256>>>(seg, edge, ws2, bs2, ws3, bs3);
    k_seggemm3<<<dim3(8, N_B), 256>>>(seg, Ws1, bs1, Ws11, bs11);
    k_uv      <<<N_B, 1024>>>();
    k_sgemm3cp<<<dim3(8, 8, N_B), 256>>>();
    k_stats   <<<dim3(4, N_B), 256>>>();
    k_bmm3    <<<dim3(8, 2, N_B), 256>>>(seg);
    k_final2  <<<dim3(8, 2, N_B), 256>>>(Wg, bg, seg, out);
}